// round 13
// baseline (speedup 1.0000x reference)
#include <cuda_runtime.h>
#include <cuda_fp16.h>
#include <math.h>
#include <stdint.h>

// ===========================================================================
// Scratch (device globals; no allocation allowed)
// B=4, S=4096, D=512 -> M = 16384
// ===========================================================================
#define MAXELEM (16384 * 512)
#define MAXPH   (4096 * 512)
#define WELEM   (512 * 512)

__device__ __align__(256) __half g_h[3][MAXELEM];     // xh, NBh, Vh
__device__ __align__(256) __half g_kq[2 * MAXELEM];   // KQ: [M, 1024]
__device__ __align__(256) __half g_wh[10][WELEM];     // Wk..Wo, WkT, WqT, Wckq(2)
__device__ __align__(256) __half2 g_cs[MAXPH];        // packed (cos,sin) base phase
__device__ float g_bc[1024];                          // combined composite bias
__device__ float g_zero[512];                         // stays zero (.bss)

// ===========================================================================
// helpers
// ===========================================================================
__device__ __forceinline__ uint32_t smem_to_u32(const void* smem_ptr) {
    uint32_t addr;
    asm("{ .reg .u64 tmp; cvta.to.shared.u64 tmp, %1; cvt.u32.u64 %0, tmp; }"
        : "=r"(addr) : "l"(smem_ptr));
    return addr;
}

__device__ __forceinline__ void ldsm_x4(uint32_t& r0, uint32_t& r1,
                                        uint32_t& r2, uint32_t& r3, uint32_t a) {
    asm volatile("ldmatrix.sync.aligned.m8n8.x4.shared.b16 {%0,%1,%2,%3}, [%4];\n"
                 : "=r"(r0), "=r"(r1), "=r"(r2), "=r"(r3) : "r"(a));
}

__device__ __forceinline__ void mma16816(float* c, const uint32_t* a,
                                         const uint32_t* b) {
    asm volatile(
        "mma.sync.aligned.m16n8k16.row.col.f32.f16.f16.f32 "
        "{%0,%1,%2,%3},{%4,%5,%6,%7},{%8,%9},{%0,%1,%2,%3};\n"
        : "+f"(c[0]), "+f"(c[1]), "+f"(c[2]), "+f"(c[3])
        : "r"(a[0]), "r"(a[1]), "r"(a[2]), "r"(a[3]), "r"(b[0]), "r"(b[1]));
}

__device__ __forceinline__ void mma16816h(uint32_t* c, const uint32_t* a,
                                          const uint32_t* b) {
    asm volatile(
        "mma.sync.aligned.m16n8k16.row.col.f16.f16.f16.f16 "
        "{%0,%1},{%2,%3,%4,%5},{%6,%7},{%0,%1};\n"
        : "+r"(c[0]), "+r"(c[1])
        : "r"(a[0]), "r"(a[1]), "r"(a[2]), "r"(a[3]), "r"(b[0]), "r"(b[1]));
}

// ===========================================================================
// Launch 0: mega elementwise kernel (cvt x + weights, phase table,
// transposes, composite biases)
// ===========================================================================
struct MegaArgs {
    const float4* x;
    const float4* w[6];
    __half2* xh;
    __half2* wh[6];
    const float* bp;
    __half2* cs;
    const float* WkF; const float* WqF;
    __half* WkT; __half* WqT;
    const float* Wkm; const float* Wqm;
    const float* bk; const float* bq;
    const float* bkm; const float* bqm;
    float* bckq;
    int x4, w4;
    int bx, bw, bt, btr;
};

__global__ void mega_kernel(MegaArgs a) {
    int blk = blockIdx.x;
    int tid = threadIdx.x;
    if (blk < a.bx) {
        int j = blk * 256 + tid;
        float4 v = a.x[j];
        a.xh[2 * j + 0] = __floats2half2_rn(v.x, v.y);
        a.xh[2 * j + 1] = __floats2half2_rn(v.z, v.w);
    } else if (blk < a.bw) {
        int q = (blk - a.bx) * 256 + tid;
        int t = q / a.w4;
        int j = q - t * a.w4;
        float4 v = a.w[t][j];
        a.wh[t][2 * j + 0] = __floats2half2_rn(v.x, v.y);
        a.wh[t][2 * j + 1] = __floats2half2_rn(v.z, v.w);
    } else if (blk < a.bt) {
        int j = (blk - a.bw) * 256 + tid;
        float s, c;
        sincosf(a.bp[j], &s, &c);
        a.cs[j] = __floats2half2_rn(c, s);
    } else if (blk < a.btr) {
        __shared__ float sm[32][33];
        int idx = blk - a.bt;
        const float* src = (idx < 256) ? a.WkF : a.WqF;
        __half* dst = (idx < 256) ? a.WkT : a.WqT;
        idx &= 255;
        int tr = idx >> 4, tc = idx & 15;
        int tx = tid & 31, ty = tid >> 5;
        #pragma unroll
        for (int i = 0; i < 4; i++)
            sm[ty + i * 8][tx] = src[(tr * 32 + ty + i * 8) * 512 + tc * 32 + tx];
        __syncthreads();
        #pragma unroll
        for (int i = 0; i < 4; i++)
            dst[(tc * 32 + ty + i * 8) * 512 + tr * 32 + tx] =
                __float2half(sm[tx][ty + i * 8]);
    } else {
        int idx = blk - a.btr;               // 0..127
        int isQ = (idx >= 64);
        const float* Wm = isQ ? a.Wqm : a.Wkm;
        const float* b1 = isQ ? a.bq  : a.bk;
        const float* b2 = isQ ? a.bqm : a.bkm;
        float* bc = a.bckq + (isQ ? 512 : 0);
        int row = (idx & 63) * 8 + (tid >> 5);
        int lane = tid & 31;
        float s = 0.f;
        #pragma unroll
        for (int j = 0; j < 16; j++)
            s += Wm[row * 512 + lane + 32 * j] * b1[lane + 32 * j];
        #pragma unroll
        for (int o = 16; o > 0; o >>= 1)
            s += __shfl_xor_sync(0xffffffffu, s, o);
        if (lane == 0) bc[row] = s + b2[row];
    }
}

// ===========================================================================
// GEMM common
// ===========================================================================
#define KC 64
#define ROWB 144
#define TILE_B (128 * ROWB)             // 18432

struct Job {
    const __half* A;
    const __half* W;
    const float*  bias;
    const float*  resid;
    float*        outF;
    __half*       outH;
    int           mode;
    int           Mj;
};

// ===========================================================================
// fp32-accumulate GEMM. 128x128 tile, 256 thr, 2 CTAs/SM, 3-stage ring.
// mode 1: fp16 out; mode 2: fp32 out + resid.
// ===========================================================================
#define STAGE_F32 (2 * TILE_B)              // 36864
#define GEMM_SMEM_F32 (3 * STAGE_F32)       // 110592

__global__ __launch_bounds__(256, 2) void gemm_h(
    Job j0, Job j1, Job j2, int N, int K)
{
    extern __shared__ char smem[];
    const Job jb = (blockIdx.z == 0) ? j0 : (blockIdx.z == 1) ? j1 : j2;

    const int bm = blockIdx.y * 128;
    if (bm >= jb.Mj) return;
    const int bn = blockIdx.x * 128;

    const uint32_t sbase = smem_to_u32(smem);
    const int tid = threadIdx.x;
    const int wid = tid >> 5, lane = tid & 31;
    const int wm = wid >> 2, wn = wid & 3;
    const int NCH = K / KC;

    const __half* Ab = jb.A + (size_t)bm * K;
    const __half* Wb = jb.W + (size_t)bn * K;

    auto load_chunk = [&](int kc, int s) {
        uint32_t st = sbase + s * STAGE_F32;
        int koff = kc * KC;
        #pragma unroll
        for (int j = 0; j < 8; j++) {
            int q = tid + j * 256;
            int t = q >> 10;
            int r = (q >> 3) & 127;
            int seg = q & 7;
            const __half* src = (t ? Wb : Ab) + (size_t)r * K + koff + seg * 8;
            uint32_t dst = st + t * TILE_B + r * ROWB + seg * 16;
            asm volatile("cp.async.cg.shared.global [%0], [%1], 16;\n"
                         :: "r"(dst), "l"(src));
        }
        asm volatile("cp.async.commit_group;\n");
    };

    float acc[4][4][4];
    #pragma unroll
    for (int i = 0; i < 4; i++)
        #pragma unroll
        for (int j = 0; j < 4; j++)
            #pragma unroll
            for (int e = 0; e < 4; e++) acc[i][j][e] = 0.f;

    load_chunk(0, 0);
    load_chunk(1, 1);

    const uint32_t a_r = (lane & 15);
    const uint32_t a_k = (lane >> 4) * 16;
    const uint32_t b_r = (lane & 7) + ((lane >> 4) << 3);
    const uint32_t b_k = ((lane >> 3) & 1) * 16;

    for (int i = 0; i < NCH; i++) {
        int s = i % 3;
        if (i == NCH - 1)
            asm volatile("cp.async.wait_group 0;\n" ::: "memory");
        else
            asm volatile("cp.async.wait_group 1;\n" ::: "memory");
        __syncthreads();
        if (i + 2 < NCH) load_chunk(i + 2, (i + 2) % 3);

        uint32_t At = sbase + s * STAGE_F32;
        uint32_t Wt = At + TILE_B;

        #pragma unroll
        for (int k16 = 0; k16 < 4; k16++) {
            uint32_t a[4][4];
            #pragma unroll
            for (int mi = 0; mi < 4; mi++) {
                uint32_t addr = At + (wm * 64 + mi * 16 + a_r) * ROWB
                              + k16 * 32 + a_k;
                ldsm_x4(a[mi][0], a[mi][1], a[mi][2], a[mi][3], addr);
            }
            uint32_t b[4][2];
            #pragma unroll
            for (int bp = 0; bp < 2; bp++) {
                uint32_t r0, r1, r2, r3;
                uint32_t addr = Wt + (wn * 32 + bp * 16 + b_r) * ROWB
                              + k16 * 32 + b_k;
                ldsm_x4(r0, r1, r2, r3, addr);
                b[2 * bp + 0][0] = r0; b[2 * bp + 0][1] = r1;
                b[2 * bp + 1][0] = r2; b[2 * bp + 1][1] = r3;
            }
            #pragma unroll
            for (int mi = 0; mi < 4; mi++)
                #pragma unroll
                for (int ni = 0; ni < 4; ni++)
                    mma16816(acc[mi][ni], a[mi], b[ni]);
        }
    }

    const int r0 = bm + wm * 64 + (lane >> 2);
    const int c0 = bn + wn * 32 + (lane & 3) * 2;
    const int mode = jb.mode;
    float2 bv[4];
    #pragma unroll
    for (int ni = 0; ni < 4; ni++)
        bv[ni] = *(const float2*)(jb.bias + c0 + ni * 8);
    #pragma unroll
    for (int mi = 0; mi < 4; mi++) {
        #pragma unroll
        for (int h = 0; h < 2; h++) {
            int row = r0 + mi * 16 + h * 8;
            #pragma unroll
            for (int ni = 0; ni < 4; ni++) {
                int col = c0 + ni * 8;
                size_t idx = (size_t)row * N + col;
                float v0 = acc[mi][ni][2 * h + 0] + bv[ni].x;
                float v1 = acc[mi][ni][2 * h + 1] + bv[ni].y;
                if (mode == 2) {
                    float2 rv = *(const float2*)(jb.resid + idx);
                    v0 += rv.x; v1 += rv.y;
                    float2 o; o.x = v0; o.y = v1;
                    *(float2*)(jb.outF + idx) = o;
                } else {
                    *(__half2*)(jb.outH + idx) = __floats2half2_rn(v0, v1);
                }
            }
        }
    }
}

// ===========================================================================
// fp16-accumulate GEMM for KM+QM combined. CTA tile 128x256, 256 thr
// (8 warps 2x4, each 64x64), 2-stage ring, 2 CTAs/SM. KQ[M,1024] fp16.
// ===========================================================================
#define TILE_B256 (256 * ROWB)                   // 36864
#define STAGE_KQ (TILE_B + TILE_B256)            // 55296
#define GEMM_SMEM_KQ (2 * STAGE_KQ)              // 110592

__global__ __launch_bounds__(256, 2) void gemm_kq(
    const __half* __restrict__ A, const __half* __restrict__ W,
    const float* __restrict__ bias, __half* __restrict__ outH,
    int M, int N, int K)
{
    extern __shared__ char smem[];
    const uint32_t sbase = smem_to_u32(smem);
    const int tid = threadIdx.x;
    const int wid = tid >> 5, lane = tid & 31;
    const int bm = blockIdx.y * 128;
    const int bn = blockIdx.x * 256;
    const int wm = wid >> 2, wn = wid & 3;
    const int NCH = K / KC;

    const __half* Ab = A + (size_t)bm * K;
    const __half* Wb = W + (size_t)bn * K;

    auto load_chunk = [&](int kc, int s) {
        uint32_t st = sbase + s * STAGE_KQ;
        int koff = kc * KC;
        #pragma unroll
        for (int j = 0; j < 12; j++) {
            int q = tid + j * 256;
            const __half* src;
            uint32_t dst;
            if (q < 1024) {
                int r = q >> 3, seg = q & 7;
                src = Ab + (size_t)r * K + koff + seg * 8;
                dst = st + r * ROWB + seg * 16;
            } else {
                int q2 = q - 1024;
                int r = q2 >> 3, seg = q2 & 7;
                src = Wb + (size_t)r * K + koff + seg * 8;
                dst = st + TILE_B + r * ROWB + seg * 16;
            }
            asm volatile("cp.async.cg.shared.global [%0], [%1], 16;\n"
                         :: "r"(dst), "l"(src));
        }
        asm volatile("cp.async.commit_group;\n");
    };

    uint32_t acc[4][8][2];
    #pragma unroll
    for (int i = 0; i < 4; i++)
        #pragma unroll
        for (int j = 0; j < 8; j++) { acc[i][j][0] = 0u; acc[i][j][1] = 0u; }

    load_chunk(0, 0);

    const uint32_t a_r = (lane & 15);
    const uint32_t a_k = (lane >> 4) * 16;
    const uint32_t b_r = (lane & 7) + ((lane >> 4) << 3);
    const uint32_t b_k = ((lane >> 3) & 1) * 16;

    for (int i = 0; i < NCH; i++) {
        int s = i & 1;
        __syncthreads();
        if (i + 1 < NCH) {
            load_chunk(i + 1, 1 - s);
            asm volatile("cp.async.wait_group 1;\n" ::: "memory");
        } else {
            asm volatile("cp.async.wait_group 0;\n" ::: "memory");
        }
        __syncthreads();

        uint32_t At = sbase + s * STAGE_KQ;
        uint32_t Wt = At + TILE_B;

        #pragma unroll
        for (int k16 = 0; k16 < 4; k16++) {
            uint32_t a[4][4];
            #pragma unroll
            for (int mi = 0; mi < 4; mi++) {
                uint32_t addr = At + (wm * 64 + mi * 16 + a_r) * ROWB
                              + k16 * 32 + a_k;
                ldsm_x4(a[mi][0], a[mi][1], a[mi][2], a[mi][3], addr);
            }
            uint32_t b[8][2];
            #pragma unroll
            for (int bp = 0; bp < 4; bp++) {
                uint32_t r0, r1, r2, r3;
                uint32_t addr = Wt + (wn * 64 + bp * 16 + b_r) * ROWB
                              + k16 * 32 + b_k;
                ldsm_x4(r0, r1, r2, r3, addr);
                b[2 * bp + 0][0] = r0; b[2 * bp + 0][1] = r1;
                b[2 * bp + 1][0] = r2; b[2 * bp + 1][1] = r3;
            }
            #pragma unroll
            for (int mi = 0; mi < 4; mi++)
                #pragma unroll
                for (int ni = 0; ni < 8; ni++)
                    mma16816h(acc[mi][ni], a[mi], b[ni]);
        }
    }

    const int r0 = bm + wm * 64 + (lane >> 2);
    const int c0 = bn + wn * 64 + (lane & 3) * 2;
    #pragma unroll
    for (int mi = 0; mi < 4; mi++) {
        #pragma unroll
        for (int h = 0; h < 2; h++) {
            int row = r0 + mi * 16 + h * 8;
            #pragma unroll
            for (int ni = 0; ni < 8; ni++) {
                int col = c0 + ni * 8;
                size_t idx = (size_t)row * N + col;
                float2 bv = *(const float2*)(bias + col);
                float2 p = __half22float2(
                    *reinterpret_cast<__half2*>(&acc[mi][ni][h]));
                *(__half2*)(outH + idx) =
                    __floats2half2_rn(p.x + bv.x, p.y + bv.y);
            }
        }
    }
}

// ===========================================================================
// Taylor sincos for tiny delta
// ===========================================================================
__device__ __forceinline__ void sincos_small(float x, float& s, float& c) {
    float x2 = x * x;
    s = x * fmaf(x2, fmaf(x2, fmaf(x2, -1.f / 5040.f, 1.f / 120.f), -1.f / 6.f), 1.f);
    c = fmaf(x2, fmaf(x2, fmaf(x2, -1.f / 720.f, 1.f / 24.f), -0.5f), 1.f);
}

// ===========================================================================
// Fused phasor + chunked cumsum + retrieval + LayerNorm -> fp16.
// v4: same as v3 but with DEPTH-2 register prefetch of all input streams
// (grid-limited occupancy -> registers are free; doubles bytes in flight).
// ===========================================================================
#define CHK 64
#define PHASOR_SMEM (CHK * 256 * 4)       // 65536 bytes

__global__ __launch_bounds__(256) void phasor_ln_kernel(
    const __half* __restrict__ V, const __half* __restrict__ KQ,
    const __half2* __restrict__ cs,
    const float* __restrict__ msp,
    const float* __restrict__ lng, const float* __restrict__ lnb,
    __half* __restrict__ Oh, int S, int D)
{
    extern __shared__ __half2 rhs[];          // [CHK][256]
    __shared__ float smu[CHK];
    __shared__ float srs[CHK];

    const int t = threadIdx.x;
    const int d0 = 2 * t;
    const int nC = S / CHK;
    const int b = blockIdx.x / nC;
    const int c = blockIdx.x % nC;

    const float ms  = msp[0];
    const float inv = rsqrtf((float)D);

    size_t base   = ((size_t)b * S + (size_t)c * CHK) * D + d0;
    size_t kqbase = ((size_t)b * S + (size_t)c * CHK) * (2 * D) + d0;
    size_t pbase  = ((size_t)c * CHK) * D + d0;

    float mr0 = 0.f, mi0 = 0.f, mr1 = 0.f, mi1 = 0.f;

    // depth-2 prefetch ring
    float2  csr[2];
    __half2 kmr[2], qmr[2], vr[2];
    #pragma unroll
    for (int p = 0; p < 2; p++) {
        csr[p] = *(const float2*)(cs + pbase + (size_t)p * D);
        kmr[p] = *(const __half2*)(KQ + kqbase + (size_t)p * 2 * D);
        qmr[p] = *(const __half2*)(KQ + kqbase + (size_t)p * 2 * D + D);
        vr[p]  = *(const __half2*)(V + base + (size_t)p * D);
    }

    #pragma unroll
    for (int s = 0; s < CHK; s++) {
        const int ring = s & 1;
        float2  cs2 = csr[ring];
        __half2 kmh = kmr[ring], qmh = qmr[ring], vh = vr[ring];
        if (s + 2 < CHK) {    // refill slot 2 ahead
            csr[ring] = *(const float2*)(cs + pbase + (size_t)(s + 2) * D);
            kmr[ring] = *(const __half2*)(KQ + kqbase + (size_t)(s + 2) * 2 * D);
            qmr[ring] = *(const __half2*)(KQ + kqbase + (size_t)(s + 2) * 2 * D + D);
            vr[ring]  = *(const __half2*)(V + base + (size_t)(s + 2) * D);
        }

        __half2 csa = *reinterpret_cast<__half2*>(&cs2.x);
        __half2 csb = *reinterpret_cast<__half2*>(&cs2.y);
        float2 c0f = __half22float2(csa);
        float2 c1f = __half22float2(csb);
        float2 km = __half22float2(kmh);
        float2 qm = __half22float2(qmh);
        float2 v2 = __half22float2(vh);

        float sk0, ck0, sq0, cq0, sk1, ck1, sq1, cq1;
        sincos_small(km.x * ms, sk0, ck0);
        sincos_small(qm.x * ms, sq0, cq0);
        sincos_small(km.y * ms, sk1, ck1);
        sincos_small(qm.y * ms, sq1, cq1);

        float ckp0 = c0f.x * ck0 - c0f.y * sk0;
        float skp0 = c0f.y * ck0 + c0f.x * sk0;
        float cqp0 = c0f.x * cq0 - c0f.y * sq0;
        float sqp0 = c0f.y * cq0 + c0f.x * sq0;
        float ckp1 = c1f.x * ck1 - c1f.y * sk1;
        float skp1 = c1f.y * ck1 + c1f.x * sk1;
        float cqp1 = c1f.x * cq1 - c1f.y * sq1;
        float sqp1 = c1f.y * cq1 + c1f.x * sq1;

        mr0 = fmaf(v2.x, ckp0, mr0);
        mi0 = fmaf(v2.x, skp0, mi0);
        mr1 = fmaf(v2.y, ckp1, mr1);
        mi1 = fmaf(v2.y, skp1, mi1);

        float rv0 = (mr0 * cqp0 + mi0 * sqp0) * inv;
        float rv1 = (mr1 * cqp1 + mi1 * sqp1) * inv;
        rhs[s * 256 + t] = __floats2half2_rn(rv0, rv1);
    }
    __syncthreads();

    // LN stats from smem: warp w handles positions 8w .. 8w+7
    {
        const int w = t >> 5, lane = t & 31;
        #pragma unroll
        for (int k = 0; k < 8; k++) {
            int s = w * 8 + k;
            float s1 = 0.f, s2 = 0.f;
            #pragma unroll
            for (int j = 0; j < 8; j++) {
                float2 f = __half22float2(rhs[s * 256 + lane + j * 32]);
                s1 += f.x + f.y;
                s2 += f.x * f.x + f.y * f.y;
            }
            #pragma unroll
            for (int o = 16; o > 0; o >>= 1) {
                s1 += __shfl_xor_sync(0xffffffffu, s1, o);
                s2 += __shfl_xor_sync(0xffffffffu, s2, o);
            }
            if (lane == 0) {
                float mu = s1 / (float)D;
                smu[s] = mu;
                srs[s] = rsqrtf(s2 / (float)D - mu * mu + 1e-5f);
            }
        }
    }
    __syncthreads();

    const float2 g  = *(const float2*)(lng + d0);
    const float2 be = *(const float2*)(lnb + d0);
    #pragma unroll
    for (int s = 0; s < CHK; s++) {
        float2 rr = __half22float2(rhs[s * 256 + t]);
        float mu = smu[s], rstd = srs[s];
        float n0 = (rr.x - mu) * rstd * g.x + be.x;
        float n1 = (rr.y - mu) * rstd * g.y + be.y;
        __stcs((__half2*)(Oh + base + (size_t)s * D),
               __floats2half2_rn(n0, n1));
    }
}

// ===========================================================================
// Launch
// ===========================================================================
extern "C" void kernel_launch(void* const* d_in, const int* in_sizes, int n_in,
                              void* d_out, int out_size)
{
    const float* x    = (const float*)d_in[0];
    const float* bp   = (const float*)d_in[1];
    const float* Wk   = (const float*)d_in[2];
    const float* bk   = (const float*)d_in[3];
    const float* Wv   = (const float*)d_in[4];
    const float* bv   = (const float*)d_in[5];
    const float* Wq   = (const float*)d_in[6];
    const float* bq   = (const float*)d_in[7];
    const float* Wkm  = (const float*)d_in[8];
    const float* bkm  = (const float*)d_in[9];
    const float* Wqm  = (const float*)d_in[10];
    const float* bqm  = (const float*)d_in[11];
    const float* ms   = (const float*)d_in[12];
    const float* lng  = (const float*)d_in[13];
    const float* lnb  = (const float*)d_in[14];
    const float* Wo   = (const float*)d_in[15];
    const float* bo   = (const float*)d_in[16];
    float* out = (float*)d_out;

    const int D  = in_sizes[3];         // 512
    const int SD = in_sizes[1];         // S*D
    const int S  = SD / D;              // 4096
    const int M  = in_sizes[0] / D;     // 16384

    __half* hp = nullptr;    cudaGetSymbolAddress((void**)&hp, g_h);
    __half* kqp = nullptr;   cudaGetSymbolAddress((void**)&kqp, g_kq);
    __half* whp = nullptr;   cudaGetSymbolAddress((void**)&whp, g_wh);
    __half2* csb = nullptr;  cudaGetSymbolAddress((void**)&csb, g_cs);
    float* bckq = nullptr;   cudaGetSymbolAddress((void**)&bckq, g_bc);
    float* zerop = nullptr;  cudaGetSymbolAddress((void**)&zerop, g_zero);

    __half* xh  = hp + 0L * MAXELEM;
    __half* NBh = hp + 1L * MAXELEM;
    __half* Vh  = hp + 2L * MAXELEM;

    __half* Wh[6];
    for (int j = 0; j < 6; j++) Wh[j] = whp + (size_t)j * WELEM;
    __half* WkT  = whp + 6L * WELEM;
    __half* WqT  = whp + 7L * WELEM;
    __half* Wckq = whp + 8L * WELEM;

    cudaFuncSetAttribute(gemm_h, cudaFuncAttributeMaxDynamicSharedMemorySize,
                         GEMM_SMEM_F32);
    cudaFuncSetAttribute(gemm_kq, cudaFuncAttributeMaxDynamicSharedMemorySize,
                         GEMM_SMEM_KQ);
    cudaFuncSetAttribute(phasor_ln_kernel,
                         cudaFuncAttributeMaxDynamicSharedMemorySize,
                         PHASOR_SMEM);

    // ---- launch 0: mega elementwise ----
    MegaArgs ma;
    ma.x = (const float4*)x;
    ma.w[0] = (const float4*)Wk;  ma.w[1] = (const float4*)Wv;
    ma.w[2] = (const float4*)Wq;  ma.w[3] = (const float4*)Wkm;
    ma.w[4] = (const float4*)Wqm; ma.w[5] = (const float4*)Wo;
    ma.xh = (__half2*)xh;
    for (int j = 0; j < 6; j++) ma.wh[j] = (__half2*)Wh[j];
    ma.bp = bp;  ma.cs = csb;
    ma.WkF = Wk; ma.WqF = Wq;
    ma.WkT = WkT; ma.WqT = WqT;
    ma.Wkm = Wkm; ma.Wqm = Wqm;
    ma.bk = bk; ma.bq = bq; ma.bkm = bkm; ma.bqm = bqm;
    ma.bckq = bckq;
    ma.x4 = M * D / 4;
    ma.w4 = WELEM / 4;
    ma.bx  = ma.x4 / 256;
    ma.bw  = ma.bx + 6 * (ma.w4 / 256);
    ma.bt  = ma.bw + SD / 256;
    ma.btr = ma.bt + 512;
    mega_kernel<<<ma.btr + 128, 256>>>(ma);

    // ---- launch 1: V + composite weights (z-jobs, early-exit M) ----
    Job jV  = { xh,    Wh[1], bv,    nullptr, nullptr, Vh, 1, M };
    Job jCk = { Wh[3], WkT,   zerop, nullptr, nullptr, Wckq, 1, D };
    Job jCq = { Wh[4], WqT,   zerop, nullptr, nullptr, Wckq + (size_t)D * D, 1, D };
    dim3 gv(D / 128, M / 128, 3);
    gemm_h<<<gv, 256, GEMM_SMEM_F32>>>(jV, jCk, jCq, D, D);

    // ---- launch 2: KQ = x @ Wckq^T + bckq (fp16 acc, 128x256 tiles) ----
    dim3 gkq(2 * D / 256, M / 128, 1);
    gemm_kq<<<gkq, 256, GEMM_SMEM_KQ>>>(xh, Wckq, bckq, kqp, M, 2 * D, D);

    // ---- launch 3: phasor + cumsum + retrieval + LayerNorm [profiled] ----
    phasor_ln_kernel<<<(M / CHK), 256, PHASOR_SMEM>>>(
        Vh, kqp, csb, ms, lng, lnb, NBh, S, D);

    // ---- launch 4: out = x + normed@Wo^T + bo ----
    Job jO = { NBh, Wh[5], bo, x, out, nullptr, 2, M };
    dim3 g1(D / 128, M / 128, 1);
    gemm_h<<<g1, 256, GEMM_SMEM_F32>>>(jO, jO, jO, D, D);
}

// round 14
// speedup vs baseline: 1.1896x; 1.1896x over previous
#include <cuda_runtime.h>
#include <cuda_fp16.h>
#include <math.h>
#include <stdint.h>

// ===========================================================================
// Scratch (device globals; no allocation allowed)
// B=4, S=4096, D=512 -> M = 16384
// ===========================================================================
#define MAXELEM (16384 * 512)
#define MAXPH   (4096 * 512)
#define WELEM   (512 * 512)

__device__ __align__(256) __half g_h[3][MAXELEM];     // xh, NBh, Vh
__device__ __align__(256) __half g_kq[2 * MAXELEM];   // KQ: [M, 1024]
__device__ __align__(256) __half g_wh[10][WELEM];     // Wk..Wo, WkT, WqT, Wckq(2)
__device__ __align__(256) __half2 g_cs[MAXPH];        // packed (cos,sin) base phase
__device__ float g_bc[1024];                          // combined composite bias
__device__ float g_zero[512];                         // stays zero (.bss)

// ===========================================================================
// helpers
// ===========================================================================
__device__ __forceinline__ uint32_t smem_to_u32(const void* smem_ptr) {
    uint32_t addr;
    asm("{ .reg .u64 tmp; cvta.to.shared.u64 tmp, %1; cvt.u32.u64 %0, tmp; }"
        : "=r"(addr) : "l"(smem_ptr));
    return addr;
}

__device__ __forceinline__ void ldsm_x4(uint32_t& r0, uint32_t& r1,
                                        uint32_t& r2, uint32_t& r3, uint32_t a) {
    asm volatile("ldmatrix.sync.aligned.m8n8.x4.shared.b16 {%0,%1,%2,%3}, [%4];\n"
                 : "=r"(r0), "=r"(r1), "=r"(r2), "=r"(r3) : "r"(a));
}

__device__ __forceinline__ void mma16816(float* c, const uint32_t* a,
                                         const uint32_t* b) {
    asm volatile(
        "mma.sync.aligned.m16n8k16.row.col.f32.f16.f16.f32 "
        "{%0,%1,%2,%3},{%4,%5,%6,%7},{%8,%9},{%0,%1,%2,%3};\n"
        : "+f"(c[0]), "+f"(c[1]), "+f"(c[2]), "+f"(c[3])
        : "r"(a[0]), "r"(a[1]), "r"(a[2]), "r"(a[3]), "r"(b[0]), "r"(b[1]));
}

__device__ __forceinline__ void mma16816h(uint32_t* c, const uint32_t* a,
                                          const uint32_t* b) {
    asm volatile(
        "mma.sync.aligned.m16n8k16.row.col.f16.f16.f16.f16 "
        "{%0,%1},{%2,%3,%4,%5},{%6,%7},{%0,%1};\n"
        : "+r"(c[0]), "+r"(c[1])
        : "r"(a[0]), "r"(a[1]), "r"(a[2]), "r"(a[3]), "r"(b[0]), "r"(b[1]));
}

// ===========================================================================
// Launch 0: mega elementwise kernel (cvt x + weights, phase table,
// transposes, composite biases)
// ===========================================================================
struct MegaArgs {
    const float4* x;
    const float4* w[6];
    __half2* xh;
    __half2* wh[6];
    const float* bp;
    __half2* cs;
    const float* WkF; const float* WqF;
    __half* WkT; __half* WqT;
    const float* Wkm; const float* Wqm;
    const float* bk; const float* bq;
    const float* bkm; const float* bqm;
    float* bckq;
    int x4, w4;
    int bx, bw, bt, btr;
};

__global__ void mega_kernel(MegaArgs a) {
    int blk = blockIdx.x;
    int tid = threadIdx.x;
    if (blk < a.bx) {
        int j = blk * 256 + tid;
        float4 v = a.x[j];
        a.xh[2 * j + 0] = __floats2half2_rn(v.x, v.y);
        a.xh[2 * j + 1] = __floats2half2_rn(v.z, v.w);
    } else if (blk < a.bw) {
        int q = (blk - a.bx) * 256 + tid;
        int t = q / a.w4;
        int j = q - t * a.w4;
        float4 v = a.w[t][j];
        a.wh[t][2 * j + 0] = __floats2half2_rn(v.x, v.y);
        a.wh[t][2 * j + 1] = __floats2half2_rn(v.z, v.w);
    } else if (blk < a.bt) {
        int j = (blk - a.bw) * 256 + tid;
        float s, c;
        __sincosf(a.bp[j], &s, &c);   // fast path: error << fp16 quantization
        a.cs[j] = __floats2half2_rn(c, s);
    } else if (blk < a.btr) {
        __shared__ float sm[32][33];
        int idx = blk - a.bt;
        const float* src = (idx < 256) ? a.WkF : a.WqF;
        __half* dst = (idx < 256) ? a.WkT : a.WqT;
        idx &= 255;
        int tr = idx >> 4, tc = idx & 15;
        int tx = tid & 31, ty = tid >> 5;
        #pragma unroll
        for (int i = 0; i < 4; i++)
            sm[ty + i * 8][tx] = src[(tr * 32 + ty + i * 8) * 512 + tc * 32 + tx];
        __syncthreads();
        #pragma unroll
        for (int i = 0; i < 4; i++)
            dst[(tc * 32 + ty + i * 8) * 512 + tr * 32 + tx] =
                __float2half(sm[tx][ty + i * 8]);
    } else {
        int idx = blk - a.btr;               // 0..127
        int isQ = (idx >= 64);
        const float* Wm = isQ ? a.Wqm : a.Wkm;
        const float* b1 = isQ ? a.bq  : a.bk;
        const float* b2 = isQ ? a.bqm : a.bkm;
        float* bc = a.bckq + (isQ ? 512 : 0);
        int row = (idx & 63) * 8 + (tid >> 5);
        int lane = tid & 31;
        float s = 0.f;
        #pragma unroll
        for (int j = 0; j < 16; j++)
            s += Wm[row * 512 + lane + 32 * j] * b1[lane + 32 * j];
        #pragma unroll
        for (int o = 16; o > 0; o >>= 1)
            s += __shfl_xor_sync(0xffffffffu, s, o);
        if (lane == 0) bc[row] = s + b2[row];
    }
}

// ===========================================================================
// GEMM common
// ===========================================================================
#define KC 64
#define ROWB 144
#define TILE_B (128 * ROWB)             // 18432

struct Job {
    const __half* A;
    const __half* W;
    const float*  bias;
    const float*  resid;
    float*        outF;
    __half*       outH;
    int           mode;
    int           Mj;
};

// ===========================================================================
// fp32-accumulate GEMM. 128x128 tile, 256 thr, 2 CTAs/SM, 3-stage ring.
// mode 1: fp16 out; mode 2: fp32 out + resid.
// ===========================================================================
#define STAGE_F32 (2 * TILE_B)              // 36864
#define GEMM_SMEM_F32 (3 * STAGE_F32)       // 110592

__global__ __launch_bounds__(256, 2) void gemm_h(
    Job j0, Job j1, Job j2, int N, int K)
{
    extern __shared__ char smem[];
    const Job jb = (blockIdx.z == 0) ? j0 : (blockIdx.z == 1) ? j1 : j2;

    const int bm = blockIdx.y * 128;
    if (bm >= jb.Mj) return;
    const int bn = blockIdx.x * 128;

    const uint32_t sbase = smem_to_u32(smem);
    const int tid = threadIdx.x;
    const int wid = tid >> 5, lane = tid & 31;
    const int wm = wid >> 2, wn = wid & 3;
    const int NCH = K / KC;

    const __half* Ab = jb.A + (size_t)bm * K;
    const __half* Wb = jb.W + (size_t)bn * K;

    auto load_chunk = [&](int kc, int s) {
        uint32_t st = sbase + s * STAGE_F32;
        int koff = kc * KC;
        #pragma unroll
        for (int j = 0; j < 8; j++) {
            int q = tid + j * 256;
            int t = q >> 10;
            int r = (q >> 3) & 127;
            int seg = q & 7;
            const __half* src = (t ? Wb : Ab) + (size_t)r * K + koff + seg * 8;
            uint32_t dst = st + t * TILE_B + r * ROWB + seg * 16;
            asm volatile("cp.async.cg.shared.global [%0], [%1], 16;\n"
                         :: "r"(dst), "l"(src));
        }
        asm volatile("cp.async.commit_group;\n");
    };

    float acc[4][4][4];
    #pragma unroll
    for (int i = 0; i < 4; i++)
        #pragma unroll
        for (int j = 0; j < 4; j++)
            #pragma unroll
            for (int e = 0; e < 4; e++) acc[i][j][e] = 0.f;

    load_chunk(0, 0);
    load_chunk(1, 1);

    const uint32_t a_r = (lane & 15);
    const uint32_t a_k = (lane >> 4) * 16;
    const uint32_t b_r = (lane & 7) + ((lane >> 4) << 3);
    const uint32_t b_k = ((lane >> 3) & 1) * 16;

    for (int i = 0; i < NCH; i++) {
        int s = i % 3;
        if (i == NCH - 1)
            asm volatile("cp.async.wait_group 0;\n" ::: "memory");
        else
            asm volatile("cp.async.wait_group 1;\n" ::: "memory");
        __syncthreads();
        if (i + 2 < NCH) load_chunk(i + 2, (i + 2) % 3);

        uint32_t At = sbase + s * STAGE_F32;
        uint32_t Wt = At + TILE_B;

        #pragma unroll
        for (int k16 = 0; k16 < 4; k16++) {
            uint32_t a[4][4];
            #pragma unroll
            for (int mi = 0; mi < 4; mi++) {
                uint32_t addr = At + (wm * 64 + mi * 16 + a_r) * ROWB
                              + k16 * 32 + a_k;
                ldsm_x4(a[mi][0], a[mi][1], a[mi][2], a[mi][3], addr);
            }
            uint32_t b[4][2];
            #pragma unroll
            for (int bp = 0; bp < 2; bp++) {
                uint32_t r0, r1, r2, r3;
                uint32_t addr = Wt + (wn * 32 + bp * 16 + b_r) * ROWB
                              + k16 * 32 + b_k;
                ldsm_x4(r0, r1, r2, r3, addr);
                b[2 * bp + 0][0] = r0; b[2 * bp + 0][1] = r1;
                b[2 * bp + 1][0] = r2; b[2 * bp + 1][1] = r3;
            }
            #pragma unroll
            for (int mi = 0; mi < 4; mi++)
                #pragma unroll
                for (int ni = 0; ni < 4; ni++)
                    mma16816(acc[mi][ni], a[mi], b[ni]);
        }
    }

    const int r0 = bm + wm * 64 + (lane >> 2);
    const int c0 = bn + wn * 32 + (lane & 3) * 2;
    const int mode = jb.mode;
    float2 bv[4];
    #pragma unroll
    for (int ni = 0; ni < 4; ni++)
        bv[ni] = *(const float2*)(jb.bias + c0 + ni * 8);
    #pragma unroll
    for (int mi = 0; mi < 4; mi++) {
        #pragma unroll
        for (int h = 0; h < 2; h++) {
            int row = r0 + mi * 16 + h * 8;
            #pragma unroll
            for (int ni = 0; ni < 4; ni++) {
                int col = c0 + ni * 8;
                size_t idx = (size_t)row * N + col;
                float v0 = acc[mi][ni][2 * h + 0] + bv[ni].x;
                float v1 = acc[mi][ni][2 * h + 1] + bv[ni].y;
                if (mode == 2) {
                    float2 rv = *(const float2*)(jb.resid + idx);
                    v0 += rv.x; v1 += rv.y;
                    float2 o; o.x = v0; o.y = v1;
                    *(float2*)(jb.outF + idx) = o;
                } else {
                    *(__half2*)(jb.outH + idx) = __floats2half2_rn(v0, v1);
                }
            }
        }
    }
}

// ===========================================================================
// fp16-accumulate GEMM for KM+QM combined. CTA tile 128x256, 256 thr
// (8 warps 2x4, each 64x64), 2-stage ring, 2 CTAs/SM. KQ[M,1024] fp16.
// ===========================================================================
#define TILE_B256 (256 * ROWB)                   // 36864
#define STAGE_KQ (TILE_B + TILE_B256)            // 55296
#define GEMM_SMEM_KQ (2 * STAGE_KQ)              // 110592

__global__ __launch_bounds__(256, 2) void gemm_kq(
    const __half* __restrict__ A, const __half* __restrict__ W,
    const float* __restrict__ bias, __half* __restrict__ outH,
    int M, int N, int K)
{
    extern __shared__ char smem[];
    const uint32_t sbase = smem_to_u32(smem);
    const int tid = threadIdx.x;
    const int wid = tid >> 5, lane = tid & 31;
    const int bm = blockIdx.y * 128;
    const int bn = blockIdx.x * 256;
    const int wm = wid >> 2, wn = wid & 3;
    const int NCH = K / KC;

    const __half* Ab = A + (size_t)bm * K;
    const __half* Wb = W + (size_t)bn * K;

    auto load_chunk = [&](int kc, int s) {
        uint32_t st = sbase + s * STAGE_KQ;
        int koff = kc * KC;
        #pragma unroll
        for (int j = 0; j < 12; j++) {
            int q = tid + j * 256;
            const __half* src;
            uint32_t dst;
            if (q < 1024) {
                int r = q >> 3, seg = q & 7;
                src = Ab + (size_t)r * K + koff + seg * 8;
                dst = st + r * ROWB + seg * 16;
            } else {
                int q2 = q - 1024;
                int r = q2 >> 3, seg = q2 & 7;
                src = Wb + (size_t)r * K + koff + seg * 8;
                dst = st + TILE_B + r * ROWB + seg * 16;
            }
            asm volatile("cp.async.cg.shared.global [%0], [%1], 16;\n"
                         :: "r"(dst), "l"(src));
        }
        asm volatile("cp.async.commit_group;\n");
    };

    uint32_t acc[4][8][2];
    #pragma unroll
    for (int i = 0; i < 4; i++)
        #pragma unroll
        for (int j = 0; j < 8; j++) { acc[i][j][0] = 0u; acc[i][j][1] = 0u; }

    load_chunk(0, 0);

    const uint32_t a_r = (lane & 15);
    const uint32_t a_k = (lane >> 4) * 16;
    const uint32_t b_r = (lane & 7) + ((lane >> 4) << 3);
    const uint32_t b_k = ((lane >> 3) & 1) * 16;

    for (int i = 0; i < NCH; i++) {
        int s = i & 1;
        __syncthreads();
        if (i + 1 < NCH) {
            load_chunk(i + 1, 1 - s);
            asm volatile("cp.async.wait_group 1;\n" ::: "memory");
        } else {
            asm volatile("cp.async.wait_group 0;\n" ::: "memory");
        }
        __syncthreads();

        uint32_t At = sbase + s * STAGE_KQ;
        uint32_t Wt = At + TILE_B;

        #pragma unroll
        for (int k16 = 0; k16 < 4; k16++) {
            uint32_t a[4][4];
            #pragma unroll
            for (int mi = 0; mi < 4; mi++) {
                uint32_t addr = At + (wm * 64 + mi * 16 + a_r) * ROWB
                              + k16 * 32 + a_k;
                ldsm_x4(a[mi][0], a[mi][1], a[mi][2], a[mi][3], addr);
            }
            uint32_t b[8][2];
            #pragma unroll
            for (int bp = 0; bp < 4; bp++) {
                uint32_t r0, r1, r2, r3;
                uint32_t addr = Wt + (wn * 64 + bp * 16 + b_r) * ROWB
                              + k16 * 32 + b_k;
                ldsm_x4(r0, r1, r2, r3, addr);
                b[2 * bp + 0][0] = r0; b[2 * bp + 0][1] = r1;
                b[2 * bp + 1][0] = r2; b[2 * bp + 1][1] = r3;
            }
            #pragma unroll
            for (int mi = 0; mi < 4; mi++)
                #pragma unroll
                for (int ni = 0; ni < 8; ni++)
                    mma16816h(acc[mi][ni], a[mi], b[ni]);
        }
    }

    const int r0 = bm + wm * 64 + (lane >> 2);
    const int c0 = bn + wn * 64 + (lane & 3) * 2;
    #pragma unroll
    for (int mi = 0; mi < 4; mi++) {
        #pragma unroll
        for (int h = 0; h < 2; h++) {
            int row = r0 + mi * 16 + h * 8;
            #pragma unroll
            for (int ni = 0; ni < 8; ni++) {
                int col = c0 + ni * 8;
                size_t idx = (size_t)row * N + col;
                float2 bv = *(const float2*)(bias + col);
                float2 p = __half22float2(
                    *reinterpret_cast<__half2*>(&acc[mi][ni][h]));
                *(__half2*)(outH + idx) =
                    __floats2half2_rn(p.x + bv.x, p.y + bv.y);
            }
        }
    }
}

// ===========================================================================
// Taylor sincos for tiny delta
// ===========================================================================
__device__ __forceinline__ void sincos_small(float x, float& s, float& c) {
    float x2 = x * x;
    s = x * fmaf(x2, fmaf(x2, fmaf(x2, -1.f / 5040.f, 1.f / 120.f), -1.f / 6.f), 1.f);
    c = fmaf(x2, fmaf(x2, fmaf(x2, -1.f / 720.f, 1.f / 24.f), -0.5f), 1.f);
}

// ===========================================================================
// Fused phasor + chunked cumsum + retrieval + LayerNorm -> fp16.
// R12 configuration (measured best: 34.5us): 256 threads (2 feats each),
// retrieved values staged in SMEM, depth-1 scalar register prefetch,
// LN stats post-loop from smem, 3 CTAs/SM.
// ===========================================================================
#define CHK 64
#define PHASOR_SMEM (CHK * 256 * 4)       // 65536 bytes

__global__ __launch_bounds__(256, 3) void phasor_ln_kernel(
    const __half* __restrict__ V, const __half* __restrict__ KQ,
    const __half2* __restrict__ cs,
    const float* __restrict__ msp,
    const float* __restrict__ lng, const float* __restrict__ lnb,
    __half* __restrict__ Oh, int S, int D)
{
    extern __shared__ __half2 rhs[];          // [CHK][256]
    __shared__ float smu[CHK];
    __shared__ float srs[CHK];

    const int t = threadIdx.x;
    const int d0 = 2 * t;
    const int nC = S / CHK;
    const int b = blockIdx.x / nC;
    const int c = blockIdx.x % nC;

    const float ms  = msp[0];
    const float inv = rsqrtf((float)D);

    size_t base   = ((size_t)b * S + (size_t)c * CHK) * D + d0;
    size_t kqbase = ((size_t)b * S + (size_t)c * CHK) * (2 * D) + d0;
    size_t pbase  = ((size_t)c * CHK) * D + d0;

    float mr0 = 0.f, mi0 = 0.f, mr1 = 0.f, mi1 = 0.f;

    // prefetch iteration 0
    float2  csr = *(const float2*)(cs + pbase);
    __half2 kmr = *(const __half2*)(KQ + kqbase);
    __half2 qmr = *(const __half2*)(KQ + kqbase + D);
    __half2 vr  = *(const __half2*)(V + base);

    #pragma unroll
    for (int s = 0; s < CHK; s++) {
        float2  cs2 = csr;
        __half2 kmh = kmr, qmh = qmr, vh = vr;
        if (s + 1 < CHK) {   // prefetch next iteration
            csr = *(const float2*)(cs + pbase + (size_t)(s + 1) * D);
            kmr = *(const __half2*)(KQ + kqbase + (size_t)(s + 1) * 2 * D);
            qmr = *(const __half2*)(KQ + kqbase + (size_t)(s + 1) * 2 * D + D);
            vr  = *(const __half2*)(V + base + (size_t)(s + 1) * D);
        }

        __half2 csa = *reinterpret_cast<__half2*>(&cs2.x);
        __half2 csb = *reinterpret_cast<__half2*>(&cs2.y);
        float2 c0f = __half22float2(csa);
        float2 c1f = __half22float2(csb);
        float2 km = __half22float2(kmh);
        float2 qm = __half22float2(qmh);
        float2 v2 = __half22float2(vh);

        float sk0, ck0, sq0, cq0, sk1, ck1, sq1, cq1;
        sincos_small(km.x * ms, sk0, ck0);
        sincos_small(qm.x * ms, sq0, cq0);
        sincos_small(km.y * ms, sk1, ck1);
        sincos_small(qm.y * ms, sq1, cq1);

        float ckp0 = c0f.x * ck0 - c0f.y * sk0;
        float skp0 = c0f.y * ck0 + c0f.x * sk0;
        float cqp0 = c0f.x * cq0 - c0f.y * sq0;
        float sqp0 = c0f.y * cq0 + c0f.x * sq0;
        float ckp1 = c1f.x * ck1 - c1f.y * sk1;
        float skp1 = c1f.y * ck1 + c1f.x * sk1;
        float cqp1 = c1f.x * cq1 - c1f.y * sq1;
        float sqp1 = c1f.y * cq1 + c1f.x * sq1;

        mr0 = fmaf(v2.x, ckp0, mr0);
        mi0 = fmaf(v2.x, skp0, mi0);
        mr1 = fmaf(v2.y, ckp1, mr1);
        mi1 = fmaf(v2.y, skp1, mi1);

        float rv0 = (mr0 * cqp0 + mi0 * sqp0) * inv;
        float rv1 = (mr1 * cqp1 + mi1 * sqp1) * inv;
        rhs[s * 256 + t] = __floats2half2_rn(rv0, rv1);
    }
    __syncthreads();

    // LN stats from smem: warp w handles positions 8w .. 8w+7
    {
        const int w = t >> 5, lane = t & 31;
        #pragma unroll
        for (int k = 0; k < 8; k++) {
            int s = w * 8 + k;
            float s1 = 0.f, s2 = 0.f;
            #pragma unroll
            for (int j = 0; j < 8; j++) {
                float2 f = __half22float2(rhs[s * 256 + lane + j * 32]);
                s1 += f.x + f.y;
                s2 += f.x * f.x + f.y * f.y;
            }
            #pragma unroll
            for (int o = 16; o > 0; o >>= 1) {
                s1 += __shfl_xor_sync(0xffffffffu, s1, o);
                s2 += __shfl_xor_sync(0xffffffffu, s2, o);
            }
            if (lane == 0) {
                float mu = s1 / (float)D;
                smu[s] = mu;
                srs[s] = rsqrtf(s2 / (float)D - mu * mu + 1e-5f);
            }
        }
    }
    __syncthreads();

    const float2 g  = *(const float2*)(lng + d0);
    const float2 be = *(const float2*)(lnb + d0);
    #pragma unroll
    for (int s = 0; s < CHK; s++) {
        float2 rr = __half22float2(rhs[s * 256 + t]);
        float mu = smu[s], rstd = srs[s];
        float n0 = (rr.x - mu) * rstd * g.x + be.x;
        float n1 = (rr.y - mu) * rstd * g.y + be.y;
        *(__half2*)(Oh + base + (size_t)s * D) = __floats2half2_rn(n0, n1);
    }
}

// ===========================================================================
// Launch
// ===========================================================================
extern "C" void kernel_launch(void* const* d_in, const int* in_sizes, int n_in,
                              void* d_out, int out_size)
{
    const float* x    = (const float*)d_in[0];
    const float* bp   = (const float*)d_in[1];
    const float* Wk   = (const float*)d_in[2];
    const float* bk   = (const float*)d_in[3];
    const float* Wv   = (const float*)d_in[4];
    const float* bv   = (const float*)d_in[5];
    const float* Wq   = (const float*)d_in[6];
    const float* bq   = (const float*)d_in[7];
    const float* Wkm  = (const float*)d_in[8];
    const float* bkm  = (const float*)d_in[9];
    const float* Wqm  = (const float*)d_in[10];
    const float* bqm  = (const float*)d_in[11];
    const float* ms   = (const float*)d_in[12];
    const float* lng  = (const float*)d_in[13];
    const float* lnb  = (const float*)d_in[14];
    const float* Wo   = (const float*)d_in[15];
    const float* bo   = (const float*)d_in[16];
    float* out = (float*)d_out;

    const int D  = in_sizes[3];         // 512
    const int SD = in_sizes[1];         // S*D
    const int S  = SD / D;              // 4096
    const int M  = in_sizes[0] / D;     // 16384

    __half* hp = nullptr;    cudaGetSymbolAddress((void**)&hp, g_h);
    __half* kqp = nullptr;   cudaGetSymbolAddress((void**)&kqp, g_kq);
    __half* whp = nullptr;   cudaGetSymbolAddress((void**)&whp, g_wh);
    __half2* csb = nullptr;  cudaGetSymbolAddress((void**)&csb, g_cs);
    float* bckq = nullptr;   cudaGetSymbolAddress((void**)&bckq, g_bc);
    float* zerop = nullptr;  cudaGetSymbolAddress((void**)&zerop, g_zero);

    __half* xh  = hp + 0L * MAXELEM;
    __half* NBh = hp + 1L * MAXELEM;
    __half* Vh  = hp + 2L * MAXELEM;

    __half* Wh[6];
    for (int j = 0; j < 6; j++) Wh[j] = whp + (size_t)j * WELEM;
    __half* WkT  = whp + 6L * WELEM;
    __half* WqT  = whp + 7L * WELEM;
    __half* Wckq = whp + 8L * WELEM;

    cudaFuncSetAttribute(gemm_h, cudaFuncAttributeMaxDynamicSharedMemorySize,
                         GEMM_SMEM_F32);
    cudaFuncSetAttribute(gemm_kq, cudaFuncAttributeMaxDynamicSharedMemorySize,
                         GEMM_SMEM_KQ);
    cudaFuncSetAttribute(phasor_ln_kernel,
                         cudaFuncAttributeMaxDynamicSharedMemorySize,
                         PHASOR_SMEM);

    // ---- launch 0: mega elementwise ----
    MegaArgs ma;
    ma.x = (const float4*)x;
    ma.w[0] = (const float4*)Wk;  ma.w[1] = (const float4*)Wv;
    ma.w[2] = (const float4*)Wq;  ma.w[3] = (const float4*)Wkm;
    ma.w[4] = (const float4*)Wqm; ma.w[5] = (const float4*)Wo;
    ma.xh = (__half2*)xh;
    for (int j = 0; j < 6; j++) ma.wh[j] = (__half2*)Wh[j];
    ma.bp = bp;  ma.cs = csb;
    ma.WkF = Wk; ma.WqF = Wq;
    ma.WkT = WkT; ma.WqT = WqT;
    ma.Wkm = Wkm; ma.Wqm = Wqm;
    ma.bk = bk; ma.bq = bq; ma.bkm = bkm; ma.bqm = bqm;
    ma.bckq = bckq;
    ma.x4 = M * D / 4;
    ma.w4 = WELEM / 4;
    ma.bx  = ma.x4 / 256;
    ma.bw  = ma.bx + 6 * (ma.w4 / 256);
    ma.bt  = ma.bw + SD / 256;
    ma.btr = ma.bt + 512;
    mega_kernel<<<ma.btr + 128, 256>>>(ma);

    // ---- launch 1: V + composite weights (z-jobs, early-exit M) ----
    Job jV  = { xh,    Wh[1], bv,    nullptr, nullptr, Vh, 1, M };
    Job jCk = { Wh[3], WkT,   zerop, nullptr, nullptr, Wckq, 1, D };
    Job jCq = { Wh[4], WqT,   zerop, nullptr, nullptr, Wckq + (size_t)D * D, 1, D };
    dim3 gv(D / 128, M / 128, 3);
    gemm_h<<<gv, 256, GEMM_SMEM_F32>>>(jV, jCk, jCq, D, D);

    // ---- launch 2: KQ = x @ Wckq^T + bckq (fp16 acc, 128x256 tiles) ----
    dim3 gkq(2 * D / 256, M / 128, 1);
    gemm_kq<<<gkq, 256, GEMM_SMEM_KQ>>>(xh, Wckq, bckq, kqp, M, 2 * D, D);

    // ---- launch 3: phasor + cumsum + retrieval + LayerNorm [profiled] ----
    phasor_ln_kernel<<<(M / CHK), 256, PHASOR_SMEM>>>(
        Vh, kqp, csb, ms, lng, lnb, NBh, S, D);

    // ---- launch 4: out = x + normed@Wo^T + bo ----
    Job jO = { NBh, Wh[5], bo, x, out, nullptr, 2, M };
    dim3 g1(D / 128, M / 128, 1);
    gemm_h<<<g1, 256, GEMM_SMEM_F32>>>(jO, jO, jO, D, D);
}